// round 11
// baseline (speedup 1.0000x reference)
#include <cuda_runtime.h>
#include <cuda_fp16.h>
#include <cstdint>
#include <cstddef>

// ---------------------------------------------------------------------------
// Shapes (fixed per reference)
// ---------------------------------------------------------------------------
#define Bb 4
#define Ss 4096
#define Dd 1024
#define Mm (Bb * Ss)   // 16384
#define Nn (2 * Dd)    // 2048
#define Kk (Dd)        // 1024

// GEMM tiling
#define TM 128
#define TN 128
#define TKC 64               // K elements per pipeline chunk (128 B rows)
#define NKC (Kk / TKC)       // 16 chunks
#define NSTAGE 3

// Scan chunking: 64-step chunks (two per GEMM row-block)
#define NCH 4096             // channels = Bb*Dd
#define CLEN 64
#define NCHUNK (Ss / CLEN)   // 64

// ---------------------------------------------------------------------------
// Static device scratch (allocation-free rule)
// ---------------------------------------------------------------------------
__device__ __half2 g_AV[(size_t)Mm * Dd];     // 64 MiB  (a_t, v_t) packed fp16
__device__ __half  g_Xh[(size_t)Mm * Kk];     // 32 MiB  fp16 of x
__device__ __half  g_Wh[(size_t)Nn * Kk];     // 4 MiB   fp16 of W, rows interleaved
__device__ float   g_Achk[NCH * NCHUNK];      // [ch][chunk]
__device__ float   g_Hend[NCH * NCHUNK];      // [ch][chunk]
__device__ float   g_Hin [NCH * NCHUNK];      // [ch][chunk]

// ---------------------------------------------------------------------------
// PTX helpers (sm_103 baseline: cp.async, ldmatrix, mma.sync)
// ---------------------------------------------------------------------------
__device__ __forceinline__ uint32_t smem_u32(const void* p) {
    return (uint32_t)__cvta_generic_to_shared(p);
}

#define CP_ASYNC16(s, g) \
    asm volatile("cp.async.cg.shared.global [%0], [%1], 16;\n" :: "r"(s), "l"(g))
#define CP_COMMIT() asm volatile("cp.async.commit_group;\n" ::: "memory")
#define CP_WAIT(n)  asm volatile("cp.async.wait_group %0;\n" :: "n"(n) : "memory")

#define LDSM_X4(r0, r1, r2, r3, a)                                              \
    asm volatile("ldmatrix.sync.aligned.m8n8.x4.shared.b16 {%0,%1,%2,%3}, [%4];" \
                 : "=r"(r0), "=r"(r1), "=r"(r2), "=r"(r3) : "r"(a))

#define MMA16816F16(d, a, b)                                                    \
    asm volatile("mma.sync.aligned.m16n8k16.row.col.f32.f16.f16.f32 "           \
                 "{%0,%1,%2,%3}, {%4,%5,%6,%7}, {%8,%9}, {%0,%1,%2,%3};"        \
                 : "+f"((d)[0]), "+f"((d)[1]), "+f"((d)[2]), "+f"((d)[3])       \
                 : "r"((a)[0]), "r"((a)[1]), "r"((a)[2]), "r"((a)[3]),          \
                   "r"((b)[0]), "r"((b)[1]))

// ---------------------------------------------------------------------------
// Gate math: a = sigmoid(-gt), v = sigmoid(gt) * g(hid)
// ---------------------------------------------------------------------------
__device__ __forceinline__ void gate_math(float gt, float hid, float& a, float& v) {
    float q = __expf(-fabsf(gt));
    float r = __fdividef(1.0f, 1.0f + q);
    float z, aa;
    if (gt >= 0.0f) { z = r;     aa = q * r; }
    else            { z = q * r; aa = r;     }
    float g;
    if (hid >= 0.0f) g = hid + 0.5f;
    else {
        float q2 = __expf(hid);
        g = __fdividef(q2, 1.0f + q2);
    }
    a = aa;
    v = z * g;
}

// ---------------------------------------------------------------------------
// Kernel 0: fp32 x -> fp16; fp32 W -> fp16 with rows interleaved:
//   Wr[2d] = W[d] (hidden row), Wr[2d+1] = W[Dd+d] (gate row)
// ---------------------------------------------------------------------------
__global__ __launch_bounds__(256) void split_kernel(const float* __restrict__ x,
                                                    const float* __restrict__ w) {
    const size_t NX4 = (size_t)Mm * Kk / 4;
    const size_t NW4 = (size_t)Nn * Kk / 4;
    size_t i = (size_t)blockIdx.x * 256 + threadIdx.x;
    if (i < NX4) {
        float4 v = ((const float4*)x)[i];
        unsigned short hs[4] = {
            __half_as_ushort(__float2half_rn(v.x)),
            __half_as_ushort(__float2half_rn(v.y)),
            __half_as_ushort(__float2half_rn(v.z)),
            __half_as_ushort(__float2half_rn(v.w))};
        *(uint2*)(g_Xh + 4 * i) = make_uint2((uint32_t)hs[0] | ((uint32_t)hs[1] << 16),
                                             (uint32_t)hs[2] | ((uint32_t)hs[3] << 16));
    } else if (i < NX4 + NW4) {
        size_t j = i - NX4;
        int e  = (int)(j >> 8);
        int c4 = (int)(j & 255);
        int er = (e < Dd) ? (2 * e) : (2 * (e - Dd) + 1);
        float4 v = ((const float4*)w)[j];
        unsigned short hs[4] = {
            __half_as_ushort(__float2half_rn(v.x)),
            __half_as_ushort(__float2half_rn(v.y)),
            __half_as_ushort(__float2half_rn(v.z)),
            __half_as_ushort(__float2half_rn(v.w))};
        *(uint2*)(g_Wh + (size_t)er * Kk + c4 * 4) =
            make_uint2((uint32_t)hs[0] | ((uint32_t)hs[1] << 16),
                       (uint32_t)hs[2] | ((uint32_t)hs[3] << 16));
    }
}

// ---------------------------------------------------------------------------
// Kernel 1: fp16 GEMM (CTA 128x128, warp tile 64x32, occ 2, TKC=64, 3 stages,
// A-fragment software pipeline) + fused gate epilogue + half-chunk summaries.
// ---------------------------------------------------------------------------
#define SOFF_XH 0
#define SOFF_WH 16384
#define STAGE_BYTES 32768
#define SMEM_DYN (NSTAGE * STAGE_BYTES)   // 96 KiB; epilogue reuses it

// epilogue smem layout (overlaps stages after sync):
//   __half2 av[128][AV_STRIDE] + float As[4][64], Hs[4][64]
#define AV_STRIDE 65
#define OFF_ASHS 33280

// 128-byte-row swizzle: 16B chunk index xor'd with row&7
__device__ __forceinline__ uint32_t sw_off(int row, int chunk) {
    return (uint32_t)(row * 128 + ((chunk ^ (row & 7)) << 4));
}

__device__ __forceinline__ void load_stage(int kc, uint32_t sb, int bm, int bn, int tid) {
    const int k0 = kc * TKC;
#pragma unroll
    for (int j = 0; j < 4; j++) {
        int q = tid + j * 256;          // 0..1023
        int row = q >> 3;               // 0..127
        int ch = q & 7;                 // 16B chunk within 128B row
        uint32_t so = sw_off(row, ch);
        size_t ga = (size_t)(bm + row) * Kk + k0 + ch * 8;
        size_t gw = (size_t)(bn + row) * Kk + k0 + ch * 8;
        CP_ASYNC16(sb + SOFF_XH + so, g_Xh + ga);
        CP_ASYNC16(sb + SOFF_WH + so, g_Wh + gw);
    }
    CP_COMMIT();
}

__global__ __launch_bounds__(256, 2) void gemm_kernel() {
    extern __shared__ char smraw[];
    const uint32_t sm0 = smem_u32(smraw);

    const int tid = threadIdx.x;
    const int wid = tid >> 5;
    const int lane = tid & 31;
    const int bm = blockIdx.y * TM;
    const int bn = blockIdx.x * TN;

    const int warp_m = (wid & 1) * 64;
    const int warp_n = (wid >> 1) * 32;

    const int lrow = lane & 15;
    const int lsel = lane >> 4;

    float acc[4][4][4];
#pragma unroll
    for (int i = 0; i < 4; i++)
#pragma unroll
        for (int j = 0; j < 4; j++)
#pragma unroll
            for (int r = 0; r < 4; r++) acc[i][j][r] = 0.0f;

    // prefetch distance 2 (one buffer always free)
    load_stage(0, sm0, bm, bn, tid);
    load_stage(1, sm0 + STAGE_BYTES, bm, bn, tid);

    uint32_t aX[2][4][4];   // double-buffered A fragments

    for (int kc = 0; kc < NKC; kc++) {
        CP_WAIT(1);
        __syncthreads();
        if (kc + 2 < NKC)
            load_stage(kc + 2, sm0 + (uint32_t)((kc + 2) % NSTAGE) * STAGE_BYTES,
                       bm, bn, tid);

        const uint32_t sb = sm0 + (uint32_t)(kc % NSTAGE) * STAGE_BYTES;

        // preload A fragments for ks = 0
#pragma unroll
        for (int mt = 0; mt < 4; mt++) {
            uint32_t so = sw_off(warp_m + mt * 16 + lrow, lsel);
            LDSM_X4(aX[0][mt][0], aX[0][mt][1], aX[0][mt][2], aX[0][mt][3],
                    sb + SOFF_XH + so);
        }

#pragma unroll
        for (int ks = 0; ks < 4; ks++) {
            const int cur = ks & 1;
            uint32_t bW[4][2];
            const int chunk = 2 * ks + lsel;
            // B fragments for this ks
#pragma unroll
            for (int ng = 0; ng < 2; ng++) {
                uint32_t so = sw_off(warp_n + ng * 16 + lrow, chunk);
                uint32_t r0, r1, r2, r3;
                LDSM_X4(r0, r1, r2, r3, sb + SOFF_WH + so);
                bW[ng * 2 + 0][0] = r0; bW[ng * 2 + 0][1] = r2;
                bW[ng * 2 + 1][0] = r1; bW[ng * 2 + 1][1] = r3;
            }
            // A fragments for ks+1 (hidden under this step's MMAs)
            if (ks < 3) {
                const int nchunk = 2 * (ks + 1) + lsel;
#pragma unroll
                for (int mt = 0; mt < 4; mt++) {
                    uint32_t so = sw_off(warp_m + mt * 16 + lrow, nchunk);
                    LDSM_X4(aX[!cur][mt][0], aX[!cur][mt][1],
                            aX[!cur][mt][2], aX[!cur][mt][3], sb + SOFF_XH + so);
                }
            }
#pragma unroll
            for (int mt = 0; mt < 4; mt++)
#pragma unroll
                for (int nt = 0; nt < 4; nt++)
                    MMA16816F16(acc[mt][nt], aX[cur][mt], bW[nt]);
        }
    }

    // ---------------- fused epilogue ----------------
    __syncthreads();                 // done with stage buffers; reuse smem
    __half2* av = (__half2*)smraw;   // [128][AV_STRIDE]
    float* As = (float*)(smraw + OFF_ASHS);          // [4][64]
    float* Hs = (float*)(smraw + OFF_ASHS + 1024);   // [4][64]

    const int erow = lane >> 2;
    const int chq  = lane & 3;
    const int wch  = warp_n >> 1;    // warp channel offset (0,16,32,48)
#pragma unroll
    for (int mt = 0; mt < 4; mt++)
#pragma unroll
        for (int nt = 0; nt < 4; nt++) {
            int rloc = warp_m + mt * 16 + erow;
            int cloc = wch + nt * 4 + chq;
            float a0, v0, a1, v1;
            gate_math(acc[mt][nt][1], acc[mt][nt][0], a0, v0);
            gate_math(acc[mt][nt][3], acc[mt][nt][2], a1, v1);
            av[rloc * AV_STRIDE + cloc]       = __floats2half2_rn(a0, v0);
            av[(rloc + 8) * AV_STRIDE + cloc] = __floats2half2_rn(a1, v1);
        }
    __syncthreads();

    // coalesced global write of the (a,v) tile: 128 rows x 64 ch x 4B
    {
        const int chbase = bn >> 1;
#pragma unroll
        for (int i = tid; i < 128 * 64; i += 256) {
            int row = i >> 6, ch = i & 63;
            g_AV[(size_t)(bm + row) * Dd + chbase + ch] = av[row * AV_STRIDE + ch];
        }
    }

    // per-32-row segment summaries
    {
        const int seg = tid >> 6;          // 0..3
        const int chl = tid & 63;          // 0..63
        float A = 1.0f, H = 0.0f;
#pragma unroll 8
        for (int i = 0; i < 32; i++) {
            float2 p = __half22float2(av[(seg * 32 + i) * AV_STRIDE + chl]);
            H = fmaf(p.x, H, p.y);
            A *= p.x;
        }
        As[seg * 64 + chl] = A;
        Hs[seg * 64 + chl] = H;
    }
    __syncthreads();
    // compose into two half-chunk (64-step) summaries, store transposed
    if (tid < 64) {
        float A0 = As[tid],       H0 = Hs[tid];
        float A1 = As[64 + tid],  H1 = Hs[64 + tid];
        float A2 = As[128 + tid], H2 = Hs[128 + tid];
        float A3 = As[192 + tid], H3 = Hs[192 + tid];
        float Ah0 = A0 * A1,  Hh0 = fmaf(A1, H0, H1);
        float Ah1 = A2 * A3,  Hh1 = fmaf(A3, H2, H3);
        const int b = bm >> 12;
        const int c2 = ((bm & (Ss - 1)) >> 7) * 2;       // half-chunk base 0..62
        const int chg = b * Dd + (bn >> 1) + tid;        // global channel
        g_Achk[chg * NCHUNK + c2]     = Ah0;
        g_Hend[chg * NCHUNK + c2]     = Hh0;
        g_Achk[chg * NCHUNK + c2 + 1] = Ah1;
        g_Hend[chg * NCHUNK + c2 + 1] = Hh1;
    }
}

// ---------------------------------------------------------------------------
// Pass 2: warp-parallel scan over 64 chunk summaries (1 warp/channel,
// 2 chunks/lane), coalesced [ch][chunk] layout.
// ---------------------------------------------------------------------------
__global__ __launch_bounds__(256) void scan_pass2() {
    int warp = (blockIdx.x * 256 + threadIdx.x) >> 5;   // channel 0..4095
    int lane = threadIdx.x & 31;
    int c0 = 2 * lane, c1 = c0 + 1;

    float A0 = g_Achk[warp * NCHUNK + c0];
    float H0 = g_Hend[warp * NCHUNK + c0];
    float A1 = g_Achk[warp * NCHUNK + c1];
    float H1 = g_Hend[warp * NCHUNK + c1];

    float Ai = A0 * A1;
    float Hi = fmaf(A1, H0, H1);

#pragma unroll
    for (int d = 1; d < 32; d <<= 1) {
        float Au = __shfl_up_sync(0xFFFFFFFFu, Ai, d);
        float Hu = __shfl_up_sync(0xFFFFFFFFu, Hi, d);
        if (lane >= d) {
            Hi = fmaf(Ai, Hu, Hi);
            Ai = Au * Ai;
        }
    }
    float Hex = __shfl_up_sync(0xFFFFFFFFu, Hi, 1);
    if (lane == 0) Hex = 0.0f;

    g_Hin[warp * NCHUNK + c0] = Hex;
    g_Hin[warp * NCHUNK + c1] = fmaf(A0, Hex, H0);
}

// ---------------------------------------------------------------------------
// Pass 3: recompute with carry-in over 64-step chunks (262144 threads).
// ---------------------------------------------------------------------------
__global__ __launch_bounds__(256) void scan_pass3(float* __restrict__ out) {
    int idx = blockIdx.x * 256 + threadIdx.x;           // 262144
    int ch = idx & (NCH - 1);
    int c  = idx >> 12;                                 // 0..63
    int b = ch >> 10, d = ch & (Dd - 1);
    size_t base = ((size_t)b * Ss + (size_t)c * CLEN) * Dd + d;
    float* orow = out + base;
    float h = g_Hin[ch * NCHUNK + c];
#pragma unroll 8
    for (int t = 0; t < CLEN; t++) {
        float2 p = __half22float2(g_AV[base]);
        base += Dd;
        h = fmaf(p.x, h, p.y);
        *orow = h;
        orow += Dd;
    }
}

// ---------------------------------------------------------------------------
extern "C" void kernel_launch(void* const* d_in, const int* in_sizes, int n_in,
                              void* d_out, int out_size)
{
    const float* x = (const float*)d_in[0];
    const float* W = (const float*)d_in[1];
    float* out = (float*)d_out;

    cudaFuncSetAttribute(gemm_kernel, cudaFuncAttributeMaxDynamicSharedMemorySize, SMEM_DYN);

    const int nsplit = (int)(((size_t)Mm * Kk / 4 + (size_t)Nn * Kk / 4) / 256);
    split_kernel<<<nsplit, 256>>>(x, W);

    gemm_kernel<<<dim3(Nn / TN, Mm / TM), 256, SMEM_DYN>>>();

    scan_pass2<<<(NCH * 32) / 256, 256>>>();
    scan_pass3<<<(NCH * NCHUNK) / 256, 256>>>(out);
}

// round 12
// speedup vs baseline: 1.0242x; 1.0242x over previous
#include <cuda_runtime.h>
#include <cuda_fp16.h>
#include <cstdint>
#include <cstddef>

// ---------------------------------------------------------------------------
// Shapes (fixed per reference)
// ---------------------------------------------------------------------------
#define Bb 4
#define Ss 4096
#define Dd 1024
#define Mm (Bb * Ss)   // 16384
#define Nn (2 * Dd)    // 2048
#define Kk (Dd)        // 1024

// GEMM tiling (R10 proven config)
#define TM 128
#define TN 128
#define TKC 64               // K elements per pipeline chunk (128 B rows)
#define NKC (Kk / TKC)       // 16 chunks
#define NSTAGE 3

// Scan chunking: 32-step chunks (four per GEMM row-block)
#define NCH 4096             // channels = Bb*Dd
#define CLEN 32
#define NCHUNK (Ss / CLEN)   // 128

// ---------------------------------------------------------------------------
// Static device scratch (allocation-free rule)
// ---------------------------------------------------------------------------
__device__ __half2 g_AV[(size_t)Mm * Dd];     // 64 MiB  (a_t, v_t) packed fp16
__device__ __half  g_Xh[(size_t)Mm * Kk];     // 32 MiB  fp16 of x
__device__ __half  g_Wh[(size_t)Nn * Kk];     // 4 MiB   fp16 of W, rows interleaved
__device__ float   g_Achk[NCH * NCHUNK];      // [ch][chunk]
__device__ float   g_Hend[NCH * NCHUNK];      // [ch][chunk]
__device__ float   g_Hin [NCH * NCHUNK];      // [ch][chunk]

// ---------------------------------------------------------------------------
// PTX helpers (sm_103 baseline: cp.async, ldmatrix, mma.sync)
// ---------------------------------------------------------------------------
__device__ __forceinline__ uint32_t smem_u32(const void* p) {
    return (uint32_t)__cvta_generic_to_shared(p);
}

#define CP_ASYNC16(s, g) \
    asm volatile("cp.async.cg.shared.global [%0], [%1], 16;\n" :: "r"(s), "l"(g))
#define CP_COMMIT() asm volatile("cp.async.commit_group;\n" ::: "memory")
#define CP_WAIT(n)  asm volatile("cp.async.wait_group %0;\n" :: "n"(n) : "memory")

#define LDSM_X4(r0, r1, r2, r3, a)                                              \
    asm volatile("ldmatrix.sync.aligned.m8n8.x4.shared.b16 {%0,%1,%2,%3}, [%4];" \
                 : "=r"(r0), "=r"(r1), "=r"(r2), "=r"(r3) : "r"(a))

#define MMA16816F16(d, a, b)                                                    \
    asm volatile("mma.sync.aligned.m16n8k16.row.col.f32.f16.f16.f32 "           \
                 "{%0,%1,%2,%3}, {%4,%5,%6,%7}, {%8,%9}, {%0,%1,%2,%3};"        \
                 : "+f"((d)[0]), "+f"((d)[1]), "+f"((d)[2]), "+f"((d)[3])       \
                 : "r"((a)[0]), "r"((a)[1]), "r"((a)[2]), "r"((a)[3]),          \
                   "r"((b)[0]), "r"((b)[1]))

// ---------------------------------------------------------------------------
// Gate math: a = sigmoid(-gt), v = sigmoid(gt) * g(hid)
// ---------------------------------------------------------------------------
__device__ __forceinline__ void gate_math(float gt, float hid, float& a, float& v) {
    float q = __expf(-fabsf(gt));
    float r = __fdividef(1.0f, 1.0f + q);
    float z, aa;
    if (gt >= 0.0f) { z = r;     aa = q * r; }
    else            { z = q * r; aa = r;     }
    float g;
    if (hid >= 0.0f) g = hid + 0.5f;
    else {
        float q2 = __expf(hid);
        g = __fdividef(q2, 1.0f + q2);
    }
    a = aa;
    v = z * g;
}

// ---------------------------------------------------------------------------
// Kernel 0: fp32 x -> fp16; fp32 W -> fp16 with rows interleaved:
//   Wr[2d] = W[d] (hidden row), Wr[2d+1] = W[Dd+d] (gate row)
// ---------------------------------------------------------------------------
__global__ __launch_bounds__(256) void split_kernel(const float* __restrict__ x,
                                                    const float* __restrict__ w) {
    const size_t NX4 = (size_t)Mm * Kk / 4;
    const size_t NW4 = (size_t)Nn * Kk / 4;
    size_t i = (size_t)blockIdx.x * 256 + threadIdx.x;
    if (i < NX4) {
        float4 v = ((const float4*)x)[i];
        unsigned short hs[4] = {
            __half_as_ushort(__float2half_rn(v.x)),
            __half_as_ushort(__float2half_rn(v.y)),
            __half_as_ushort(__float2half_rn(v.z)),
            __half_as_ushort(__float2half_rn(v.w))};
        *(uint2*)(g_Xh + 4 * i) = make_uint2((uint32_t)hs[0] | ((uint32_t)hs[1] << 16),
                                             (uint32_t)hs[2] | ((uint32_t)hs[3] << 16));
    } else if (i < NX4 + NW4) {
        size_t j = i - NX4;
        int e  = (int)(j >> 8);
        int c4 = (int)(j & 255);
        int er = (e < Dd) ? (2 * e) : (2 * (e - Dd) + 1);
        float4 v = ((const float4*)w)[j];
        unsigned short hs[4] = {
            __half_as_ushort(__float2half_rn(v.x)),
            __half_as_ushort(__float2half_rn(v.y)),
            __half_as_ushort(__float2half_rn(v.z)),
            __half_as_ushort(__float2half_rn(v.w))};
        *(uint2*)(g_Wh + (size_t)er * Kk + c4 * 4) =
            make_uint2((uint32_t)hs[0] | ((uint32_t)hs[1] << 16),
                       (uint32_t)hs[2] | ((uint32_t)hs[3] << 16));
    }
}

// ---------------------------------------------------------------------------
// Kernel 1: fp16 GEMM (CTA 128x128, warp tile 64x32, occ 2, TKC=64, 3 stages)
//           + fused gate epilogue + per-32-row chunk summaries.
// ---------------------------------------------------------------------------
#define SOFF_XH 0
#define SOFF_WH 16384
#define STAGE_BYTES 32768
#define SMEM_DYN (NSTAGE * STAGE_BYTES)   // 96 KiB; epilogue reuses it

// epilogue smem layout (overlaps stages after sync):
//   __half2 av[128][AV_STRIDE]
#define AV_STRIDE 65

// 128-byte-row swizzle: 16B chunk index xor'd with row&7
__device__ __forceinline__ uint32_t sw_off(int row, int chunk) {
    return (uint32_t)(row * 128 + ((chunk ^ (row & 7)) << 4));
}

__device__ __forceinline__ void load_stage(int kc, uint32_t sb, int bm, int bn, int tid) {
    const int k0 = kc * TKC;
#pragma unroll
    for (int j = 0; j < 4; j++) {
        int q = tid + j * 256;          // 0..1023
        int row = q >> 3;               // 0..127
        int ch = q & 7;                 // 16B chunk within 128B row
        uint32_t so = sw_off(row, ch);
        size_t ga = (size_t)(bm + row) * Kk + k0 + ch * 8;
        size_t gw = (size_t)(bn + row) * Kk + k0 + ch * 8;
        CP_ASYNC16(sb + SOFF_XH + so, g_Xh + ga);
        CP_ASYNC16(sb + SOFF_WH + so, g_Wh + gw);
    }
    CP_COMMIT();
}

__global__ __launch_bounds__(256, 2) void gemm_kernel() {
    extern __shared__ char smraw[];
    const uint32_t sm0 = smem_u32(smraw);

    const int tid = threadIdx.x;
    const int wid = tid >> 5;
    const int lane = tid & 31;
    const int bm = blockIdx.y * TM;
    const int bn = blockIdx.x * TN;

    const int warp_m = (wid & 1) * 64;
    const int warp_n = (wid >> 1) * 32;

    const int lrow = lane & 15;
    const int lsel = lane >> 4;

    float acc[4][4][4];
#pragma unroll
    for (int i = 0; i < 4; i++)
#pragma unroll
        for (int j = 0; j < 4; j++)
#pragma unroll
            for (int r = 0; r < 4; r++) acc[i][j][r] = 0.0f;

    // prefetch distance 2 (one buffer always free)
    load_stage(0, sm0, bm, bn, tid);
    load_stage(1, sm0 + STAGE_BYTES, bm, bn, tid);

    for (int kc = 0; kc < NKC; kc++) {
        CP_WAIT(1);
        __syncthreads();
        if (kc + 2 < NKC)
            load_stage(kc + 2, sm0 + (uint32_t)((kc + 2) % NSTAGE) * STAGE_BYTES,
                       bm, bn, tid);

        const uint32_t sb = sm0 + (uint32_t)(kc % NSTAGE) * STAGE_BYTES;
#pragma unroll
        for (int ks = 0; ks < 4; ks++) {
            uint32_t aX[4][4], bW[4][2];
            const int chunk = 2 * ks + lsel;
#pragma unroll
            for (int mt = 0; mt < 4; mt++) {
                uint32_t so = sw_off(warp_m + mt * 16 + lrow, chunk);
                LDSM_X4(aX[mt][0], aX[mt][1], aX[mt][2], aX[mt][3], sb + SOFF_XH + so);
            }
#pragma unroll
            for (int ng = 0; ng < 2; ng++) {
                uint32_t so = sw_off(warp_n + ng * 16 + lrow, chunk);
                uint32_t r0, r1, r2, r3;
                LDSM_X4(r0, r1, r2, r3, sb + SOFF_WH + so);
                bW[ng * 2 + 0][0] = r0; bW[ng * 2 + 0][1] = r2;
                bW[ng * 2 + 1][0] = r1; bW[ng * 2 + 1][1] = r3;
            }
#pragma unroll
            for (int mt = 0; mt < 4; mt++)
#pragma unroll
                for (int nt = 0; nt < 4; nt++)
                    MMA16816F16(acc[mt][nt], aX[mt], bW[nt]);
        }
    }

    // ---------------- fused epilogue ----------------
    __syncthreads();                 // done with stage buffers; reuse smem
    __half2* av = (__half2*)smraw;   // [128][AV_STRIDE]

    const int erow = lane >> 2;
    const int chq  = lane & 3;
    const int wch  = warp_n >> 1;    // warp channel offset (0,16,32,48)
#pragma unroll
    for (int mt = 0; mt < 4; mt++)
#pragma unroll
        for (int nt = 0; nt < 4; nt++) {
            int rloc = warp_m + mt * 16 + erow;
            int cloc = wch + nt * 4 + chq;
            float a0, v0, a1, v1;
            gate_math(acc[mt][nt][1], acc[mt][nt][0], a0, v0);
            gate_math(acc[mt][nt][3], acc[mt][nt][2], a1, v1);
            av[rloc * AV_STRIDE + cloc]       = __floats2half2_rn(a0, v0);
            av[(rloc + 8) * AV_STRIDE + cloc] = __floats2half2_rn(a1, v1);
        }
    __syncthreads();

    // coalesced global write of the (a,v) tile: 128 rows x 64 ch x 4B
    {
        const int chbase = bn >> 1;
#pragma unroll
        for (int i = tid; i < 128 * 64; i += 256) {
            int row = i >> 6, ch = i & 63;
            g_AV[(size_t)(bm + row) * Dd + chbase + ch] = av[row * AV_STRIDE + ch];
        }
    }

    // per-32-row chunk summaries (4 chunks per CTA), stored transposed
    {
        const int seg = tid >> 6;          // 0..3
        const int chl = tid & 63;          // 0..63
        float A = 1.0f, H = 0.0f;
#pragma unroll 8
        for (int i = 0; i < 32; i++) {
            float2 p = __half22float2(av[(seg * 32 + i) * AV_STRIDE + chl]);
            H = fmaf(p.x, H, p.y);
            A *= p.x;
        }
        const int b = bm >> 12;
        const int c = ((bm & (Ss - 1)) >> 5) + seg;      // chunk index 0..127
        const int chg = b * Dd + (bn >> 1) + chl;        // global channel
        g_Achk[chg * NCHUNK + c] = A;
        g_Hend[chg * NCHUNK + c] = H;
    }
}

// ---------------------------------------------------------------------------
// Pass 2: warp-parallel scan over 128 chunk summaries (1 warp/channel,
// 4 chunks/lane), coalesced [ch][chunk] layout.
// ---------------------------------------------------------------------------
__global__ __launch_bounds__(256) void scan_pass2() {
    int warp = (blockIdx.x * 256 + threadIdx.x) >> 5;   // channel 0..4095
    int lane = threadIdx.x & 31;
    const int c0 = 4 * lane;

    float4 Av = *(const float4*)(g_Achk + warp * NCHUNK + c0);
    float4 Hv = *(const float4*)(g_Hend + warp * NCHUNK + c0);

    // compose the 4 local chunks: running prefix within the lane
    float A01 = Av.x * Av.y;
    float H01 = fmaf(Av.y, Hv.x, Hv.y);
    float A012 = A01 * Av.z;
    float H012 = fmaf(Av.z, H01, Hv.z);
    float Ai = A012 * Av.w;
    float Hi = fmaf(Av.w, H012, Hv.w);

#pragma unroll
    for (int d = 1; d < 32; d <<= 1) {
        float Au = __shfl_up_sync(0xFFFFFFFFu, Ai, d);
        float Hu = __shfl_up_sync(0xFFFFFFFFu, Hi, d);
        if (lane >= d) {
            Hi = fmaf(Ai, Hu, Hi);
            Ai = Au * Ai;
        }
    }
    float Hex = __shfl_up_sync(0xFFFFFFFFu, Hi, 1);
    if (lane == 0) Hex = 0.0f;

    // carry-ins for the 4 local chunks
    float4 Hin;
    Hin.x = Hex;
    Hin.y = fmaf(Av.x, Hex, Hv.x);     // after chunk c0
    Hin.z = fmaf(A01,  Hex, H01);      // after c0,c0+1
    Hin.w = fmaf(A012, Hex, H012);     // after c0..c0+2
    *(float4*)(g_Hin + warp * NCHUNK + c0) = Hin;
}

// ---------------------------------------------------------------------------
// Pass 3: recompute with carry-in over 32-step chunks (524288 threads).
// ---------------------------------------------------------------------------
__global__ __launch_bounds__(256) void scan_pass3(float* __restrict__ out) {
    int idx = blockIdx.x * 256 + threadIdx.x;           // 524288
    int ch = idx & (NCH - 1);
    int c  = idx >> 12;                                 // 0..127
    int b = ch >> 10, d = ch & (Dd - 1);
    size_t base = ((size_t)b * Ss + (size_t)c * CLEN) * Dd + d;
    float* orow = out + base;
    float h = g_Hin[ch * NCHUNK + c];
#pragma unroll 8
    for (int t = 0; t < CLEN; t++) {
        float2 p = __half22float2(g_AV[base]);
        base += Dd;
        h = fmaf(p.x, h, p.y);
        *orow = h;
        orow += Dd;
    }
}

// ---------------------------------------------------------------------------
extern "C" void kernel_launch(void* const* d_in, const int* in_sizes, int n_in,
                              void* d_out, int out_size)
{
    const float* x = (const float*)d_in[0];
    const float* W = (const float*)d_in[1];
    float* out = (float*)d_out;

    cudaFuncSetAttribute(gemm_kernel, cudaFuncAttributeMaxDynamicSharedMemorySize, SMEM_DYN);

    const int nsplit = (int)(((size_t)Mm * Kk / 4 + (size_t)Nn * Kk / 4) / 256);
    split_kernel<<<nsplit, 256>>>(x, W);

    gemm_kernel<<<dim3(Nn / TN, Mm / TM), 256, SMEM_DYN>>>();

    scan_pass2<<<(NCH * 32) / 256, 256>>>();
    scan_pass3<<<(NCH * NCHUNK) / 256, 256>>>(out);
}